// round 10
// baseline (speedup 1.0000x reference)
#include <cuda_runtime.h>
#include <cuda_bf16.h>
#include <math.h>

#define BATCH   2
#define SEQ     2048
#define DMODEL  1024
#define NHEAD   16
#define HDIM    64
#define BH      (BATCH*NHEAD)      // 32
#define ROWS    (BATCH*SEQ)        // 4096
#define U_TOP   38                 // int(5 * ln(2048)) = 38
#define CCAP    192                // candidate buffer per row

typedef unsigned long long ull;

// ---- packed f32x2 helpers ---------------------------------------------------
__device__ __forceinline__ ull pk2(float x, float y) {
    ull r; asm("mov.b64 %0, {%1, %2};" : "=l"(r) : "f"(x), "f"(y)); return r;
}
__device__ __forceinline__ void ffma2(ull& d, ull a, ull b) {
    asm("fma.rn.f32x2 %0, %1, %2, %0;" : "+l"(d) : "l"(a), "l"(b));
}
__device__ __forceinline__ float2 up2(ull v) {
    float2 f; asm("mov.b64 {%0, %1}, %2;" : "=f"(f.x), "=f"(f.y) : "l"(v)); return f;
}
union f4u { float4 f; ull u[2]; };

// ---------------- scratch ----------------------------------------------------
__device__ __align__(256) float g_Q[ROWS * DMODEL];
__device__ __align__(256) float g_Kp[ROWS * DMODEL];
__device__ __align__(256) float g_Vp[ROWS * DMODEL];
__device__ __align__(256) float g_ctx[ROWS * DMODEL];

// =================== FFMA2 SGEMM, 16m x 8n per thread (R9, measured) =========
#define GBM 256
#define GBN 128
#define GBK 16

__device__ __forceinline__
void gemm_body(const float* __restrict__ A, const float* __restrict__ Bw,
               const float* __restrict__ bias, float* __restrict__ C,
               int m0, int n0, int K, int N)
{
    __shared__ float As[GBK][GBM];
    __shared__ float Bs[GBK][GBN];

    const int tid = threadIdx.x;
    const int tx = tid & 15;
    const int ty = tid >> 4;

    ull acc2[8][8];
#pragma unroll
    for (int i = 0; i < 8; i++)
#pragma unroll
        for (int j = 0; j < 8; j++) acc2[i][j] = 0ull;

    for (int k0 = 0; k0 < K; k0 += GBK) {
#pragma unroll
        for (int i = 0; i < 4; i++) {
            int fidx = tid + i * 256;
            int row  = fidx >> 2;
            int kq   = fidx & 3;
            float4 va = *(const float4*)(A + (size_t)(m0 + row) * K + k0 + kq * 4);
            As[kq*4+0][row] = va.x; As[kq*4+1][row] = va.y;
            As[kq*4+2][row] = va.z; As[kq*4+3][row] = va.w;
        }
#pragma unroll
        for (int i = 0; i < 2; i++) {
            int fidx = tid + i * 256;
            int row  = fidx >> 2;
            int kq   = fidx & 3;
            float4 vb = *(const float4*)(Bw + (size_t)(n0 + row) * K + k0 + kq * 4);
            Bs[kq*4+0][row] = vb.x; Bs[kq*4+1][row] = vb.y;
            Bs[kq*4+2][row] = vb.z; Bs[kq*4+3][row] = vb.w;
        }
        __syncthreads();
#pragma unroll
        for (int kk = 0; kk < GBK; kk++) {
            f4u a4[4];
#pragma unroll
            for (int c = 0; c < 4; c++)
                a4[c].f = *(float4*)&As[kk][ty * 16 + c * 4];
            float bf[8];
            *(float4*)&bf[0] = *(float4*)&Bs[kk][tx * 8];
            *(float4*)&bf[4] = *(float4*)&Bs[kk][tx * 8 + 4];
            ull bd[8];
#pragma unroll
            for (int j = 0; j < 8; j++) bd[j] = pk2(bf[j], bf[j]);
#pragma unroll
            for (int mp = 0; mp < 8; mp++) {
                ull ap = a4[mp >> 1].u[mp & 1];
#pragma unroll
                for (int j = 0; j < 8; j++) ffma2(acc2[mp][j], ap, bd[j]);
            }
        }
        __syncthreads();
    }

    float bc[8];
#pragma unroll
    for (int j = 0; j < 8; j++) bc[j] = bias[n0 + tx * 8 + j];

#pragma unroll
    for (int mp = 0; mp < 8; mp++) {
        const int rowe = m0 + ty * 16 + mp * 2;
        float2 p[8];
#pragma unroll
        for (int j = 0; j < 8; j++) p[j] = up2(acc2[mp][j]);
        float4 e0 = make_float4(p[0].x + bc[0], p[1].x + bc[1], p[2].x + bc[2], p[3].x + bc[3]);
        float4 e1 = make_float4(p[4].x + bc[4], p[5].x + bc[5], p[6].x + bc[6], p[7].x + bc[7]);
        float4 o0 = make_float4(p[0].y + bc[0], p[1].y + bc[1], p[2].y + bc[2], p[3].y + bc[3]);
        float4 o1 = make_float4(p[4].y + bc[4], p[5].y + bc[5], p[6].y + bc[6], p[7].y + bc[7]);
        float* r0 = C + (size_t)rowe * N + n0 + tx * 8;
        float* r1 = C + (size_t)(rowe + 1) * N + n0 + tx * 8;
        *(float4*)(r0)     = e0;  *(float4*)(r0 + 4) = e1;
        *(float4*)(r1)     = o0;  *(float4*)(r1 + 4) = o1;
    }
}

__global__ __launch_bounds__(256)
void qkv_gemm(const float* __restrict__ x,
              const float* __restrict__ Wq, const float* __restrict__ bq, float* __restrict__ Q,
              const float* __restrict__ Wk, const float* __restrict__ bk, float* __restrict__ K,
              const float* __restrict__ Wv, const float* __restrict__ bv, float* __restrict__ V)
{
    const int sel = blockIdx.z;
    const float* W = (sel == 0) ? Wq : (sel == 1) ? Wk : Wv;
    const float* b = (sel == 0) ? bq : (sel == 1) ? bk : bv;
    float*       C = (sel == 0) ? Q  : (sel == 1) ? K  : V;
    gemm_body(x, W, b, C, blockIdx.y * GBM, blockIdx.x * GBN, DMODEL, DMODEL);
}

__global__ __launch_bounds__(256)
void out_gemm(const float* __restrict__ A, const float* __restrict__ W,
              const float* __restrict__ b, float* __restrict__ C)
{
    gemm_body(A, W, b, C, blockIdx.y * GBM, blockIdx.x * GBN, DMODEL, DMODEL);
}

// ---------------- fused ProbSparse attention (R8 version, measured) ----------
// 512 threads. Phase 1: 4q x 4k register tile, KT=512 k-rows per tile,
// head dim split in two 32-wide chunks; next chunk's K prefetched to registers.
#define TQ 16
#define KT 512
#define ATHREADS 512
#define NCC (SEQ / KT * 2)          // 8 chunk-iterations (4 kt x 2 d-chunks)

__device__ __forceinline__ unsigned fkey(float x) {
    unsigned u = __float_as_uint(x);
    return (u & 0x80000000u) ? ~u : (u | 0x80000000u);
}
__device__ __forceinline__ float unfkey(unsigned k) {
    unsigned u = (k & 0x80000000u) ? (k ^ 0x80000000u) : ~k;
    return __uint_as_float(u);
}

__device__ unsigned radix_select(const float* __restrict__ Srow,
                                 unsigned* __restrict__ myhist, int lane)
{
    unsigned prefix = 0;
    int remaining = U_TOP;
    for (int pass = 0; pass < 4; pass++) {
        const int shift = 24 - pass * 8;
#pragma unroll
        for (int j = 0; j < 8; j++) myhist[lane * 8 + j] = 0;
        __syncwarp();
        for (int i = lane; i < SEQ; i += 32) {
            unsigned key = fkey(Srow[i]);
            bool ok = (pass == 0) || ((key >> (shift + 8)) == prefix);
            if (ok) atomicAdd(&myhist[(key >> shift) & 255], 1u);
        }
        __syncwarp();
        unsigned psum = 0;
#pragma unroll
        for (int j = 0; j < 8; j++) psum += myhist[lane * 8 + j];
        unsigned c = psum;
#pragma unroll
        for (int off = 1; off < 32; off <<= 1) {
            unsigned o = __shfl_down_sync(0xffffffffu, c, off);
            if (lane + off < 32) c += o;
        }
        unsigned mk = __ballot_sync(0xffffffffu, c >= (unsigned)remaining);
        int lsel = 31 - __clz(mk);
        int digit = 0, newrem = remaining;
        if (lane == lsel) {
            unsigned cum = c - psum;
            for (int j = 7; j >= 0; j--) {
                unsigned hv = myhist[lsel * 8 + j];
                cum += hv;
                if (cum >= (unsigned)remaining) {
                    digit = lsel * 8 + j;
                    newrem = remaining - (int)(cum - hv);
                    break;
                }
            }
        }
        digit  = __shfl_sync(0xffffffffu, digit, lsel);
        newrem = __shfl_sync(0xffffffffu, newrem, lsel);
        prefix = (prefix << 8) | (unsigned)digit;
        remaining = newrem;
        __syncwarp();
    }
    return prefix;
}

// smem: S[16*2048] | Qs[16*64] | Ks[512*32 swizzled] | wbuf[16 warps * 384 u32]
#define ATTN_SMEM_BYTES ((TQ*SEQ + TQ*64 + KT*32) * 4 + 16*384*4)

__global__ __launch_bounds__(ATHREADS)
void attn_kernel(const float* __restrict__ Q, const float* __restrict__ K,
                 const float* __restrict__ V, float* __restrict__ ctx)
{
    extern __shared__ char smraw[];
    float*    S    = (float*)smraw;
    float*    Qs   = S  + TQ * SEQ;
    float*    Ks   = Qs + TQ * 64;                 // 512 rows x 32 floats, swizzled
    unsigned* wbuf = (unsigned*)(Ks + KT * 32);    // 16 * 384

    const int tid = threadIdx.x;
    const int qt  = blockIdx.x;
    const int bh  = blockIdx.y;
    const int b   = bh >> 4, h = bh & 15;
    const int q0  = qt * TQ;

    const float* Qbase = Q + ((size_t)b * SEQ + q0) * DMODEL + h * HDIM;
    const float* Kbase = K + ((size_t)b * SEQ) * DMODEL + h * HDIM;
    const float* Vbase = V + ((size_t)b * SEQ) * DMODEL + h * HDIM;

    // load Q tile (16 rows x 64)
    if (tid < 256) {
        int row = tid >> 4, c4 = tid & 15;
        *(float4*)(Qs + row * 64 + c4 * 4) =
            *(const float4*)(Qbase + (size_t)row * DMODEL + c4 * 4);
    }

    // ---- phase 1: scores, 4q x 4k per thread ----
    const int kq  = tid & 127;     // k-group (4 consecutive k rows)
    const int qg  = tid >> 7;      // q-group (4 consecutive q rows), 0..3
    const int swz = kq & 7;

    const int prow = tid >> 3;
    const int pd4  = tid & 7;

    float4 st[8];
#pragma unroll
    for (int i = 0; i < 8; i++) {
        int row = i * 64 + prow;
        st[i] = *(const float4*)(Kbase + (size_t)row * DMODEL + pd4 * 4);
    }

    ull acc2[4][4];

    for (int cc = 0; cc < NCC; cc++) {
        const int ch = cc & 1;
        const int kb = (cc >> 1) * KT;

        __syncthreads();
#pragma unroll
        for (int i = 0; i < 8; i++) {
            int row = i * 64 + prow;
            *(float4*)(Ks + row * 32 + ((pd4 ^ ((row >> 2) & 7)) << 2)) = st[i];
        }
        if (cc + 1 < NCC) {
            const int nch = (cc + 1) & 1;
            const int nkb = ((cc + 1) >> 1) * KT;
#pragma unroll
            for (int i = 0; i < 8; i++) {
                int row = i * 64 + prow;
                st[i] = *(const float4*)(Kbase + (size_t)(nkb + row) * DMODEL
                                         + nch * 32 + pd4 * 4);
            }
        }
        __syncthreads();

        if (ch == 0) {
#pragma unroll
            for (int j = 0; j < 4; j++)
#pragma unroll
                for (int i = 0; i < 4; i++) acc2[j][i] = 0ull;
        }

#pragma unroll
        for (int d4 = 0; d4 < 8; d4++) {
            f4u kv[4];
#pragma unroll
            for (int i = 0; i < 4; i++)
                kv[i].f = *(float4*)(Ks + (kq * 4 + i) * 32 + ((d4 ^ swz) << 2));
#pragma unroll
            for (int j = 0; j < 4; j++) {
                f4u qv;
                qv.f = *(float4*)(Qs + (qg * 4 + j) * 64 + ch * 32 + (d4 << 2));
#pragma unroll
                for (int i = 0; i < 4; i++) {
                    ffma2(acc2[j][i], qv.u[0], kv[i].u[0]);
                    ffma2(acc2[j][i], qv.u[1], kv[i].u[1]);
                }
            }
        }

        if (ch == 1) {
#pragma unroll
            for (int j = 0; j < 4; j++) {
                float2 r0 = up2(acc2[j][0]), r1 = up2(acc2[j][1]);
                float2 r2 = up2(acc2[j][2]), r3 = up2(acc2[j][3]);
                float4 o = make_float4((r0.x + r0.y) * 0.125f, (r1.x + r1.y) * 0.125f,
                                       (r2.x + r2.y) * 0.125f, (r3.x + r3.y) * 0.125f);
                *(float4*)(S + (size_t)(qg * 4 + j) * SEQ + kb + kq * 4) = o;
            }
        }
    }
    __syncthreads();

    // ---- phase 2: 1 row per warp ----
    const int lane = tid & 31, wid = tid >> 5;
    const unsigned lmlt = (1u << lane) - 1u;
    unsigned* chk = wbuf + wid * 384;
    int*      chi = (int*)(chk + CCAP);
    unsigned* myhist = chk;

    {
        const int q = wid;
        const float* Srow = S + (size_t)q * SEQ;

        float lm = -1e30f;
        for (int i = lane; i < SEQ; i += 32) lm = fmaxf(lm, Srow[i]);
        float m = lm, tmin = lm;
#pragma unroll
        for (int off = 16; off; off >>= 1) {
            m    = fmaxf(m,    __shfl_xor_sync(0xffffffffu, m,    off));
            tmin = fminf(tmin, __shfl_xor_sync(0xffffffffu, tmin, off));
        }
        const unsigned Tk = fkey(tmin);

        int cnt = 0;
        for (int base = 0; base < SEQ; base += 32) {
            int i = base + lane;
            unsigned key = fkey(Srow[i]);
            bool kp = key >= Tk;
            unsigned bm = __ballot_sync(0xffffffffu, kp);
            if (kp) {
                int pos = cnt + __popc(bm & lmlt);
                if (pos < CCAP) { chk[pos] = key; chi[pos] = i; }
            }
            cnt += __popc(bm);
        }
        __syncwarp();

        const bool okc = (cnt >= U_TOP && cnt <= CCAP);
        unsigned kth;
        if (okc) {
            unsigned ck[6];
#pragma unroll
            for (int t = 0; t < 6; t++) {
                int p = lane + t * 32;
                ck[t] = (p < cnt) ? chk[p] : 0u;
            }
            unsigned lo = Tk, hi = fkey(m);
            while (lo < hi) {
                unsigned mid = lo + ((hi - lo + 1) >> 1);
                int c = 0;
#pragma unroll
                for (int t = 0; t < 6; t++) c += (ck[t] >= mid) ? 1 : 0;
                c = __reduce_add_sync(0xffffffffu, c);
                if (c >= U_TOP) lo = mid; else hi = mid - 1;
            }
            kth = lo;
        } else {
            kth = radix_select(Srow, myhist, lane);
        }

        float lsum = 0.f;
        int nk = 0;
        if (okc) {
            for (int base = 0; base < cnt; base += 32) {
                int p = base + lane;
                unsigned key = (p < cnt) ? chk[p] : 0u;
                int idx      = (p < cnt) ? chi[p] : 0;
                __syncwarp();
                bool kp = (p < cnt) && (key >= kth);
                unsigned bm = __ballot_sync(0xffffffffu, kp);
                if (kp) {
                    float w = __expf(unfkey(key) - m);
                    lsum += w;
                    int pos = nk + __popc(bm & lmlt);
                    chi[pos] = idx;
                    chk[pos] = __float_as_uint(w);
                }
                nk += __popc(bm);
            }
        } else {
            for (int base = 0; base < SEQ; base += 32) {
                int i = base + lane;
                float s = Srow[i];
                bool kp = fkey(s) >= kth;
                unsigned bm = __ballot_sync(0xffffffffu, kp);
                if (kp) {
                    float w = __expf(s - m);
                    lsum += w;
                    int pos = nk + __popc(bm & lmlt);
                    if (pos < CCAP) { chi[pos] = i; chk[pos] = __float_as_uint(w); }
                }
                nk += __popc(bm);
            }
        }
        __syncwarp();
#pragma unroll
        for (int off = 16; off; off >>= 1)
            lsum += __shfl_xor_sync(0xffffffffu, lsum, off);
        const float scale = 1.f / lsum;

        float c0 = 0.f, c1 = 0.f;
        if (nk <= CCAP) {
            for (int j = 0; j < nk; j++) {
                int kkidx = chi[j];
                float w = __uint_as_float(chk[j]);
                const float* vr = Vbase + (size_t)kkidx * DMODEL;
                c0 += w * vr[lane];
                c1 += w * vr[lane + 32];
            }
        } else {
            for (int i = 0; i < SEQ; i++) {
                float s = Srow[i];
                if (fkey(s) >= kth) {
                    float w = __expf(s - m);
                    const float* vr = Vbase + (size_t)i * DMODEL;
                    c0 += w * vr[lane];
                    c1 += w * vr[lane + 32];
                }
            }
        }
        float* orow = ctx + ((size_t)b * SEQ + q0 + q) * DMODEL + h * HDIM;
        orow[lane]      = c0 * scale;
        orow[lane + 32] = c1 * scale;
    }
}

// ---------------- launch ----------------------------------------------------
extern "C" void kernel_launch(void* const* d_in, const int* in_sizes, int n_in,
                              void* d_out, int out_size)
{
    const float* x  = (const float*)d_in[0];
    const float* Wq = (const float*)d_in[1];
    const float* bq = (const float*)d_in[2];
    const float* Wk = (const float*)d_in[3];
    const float* bk = (const float*)d_in[4];
    const float* Wv = (const float*)d_in[5];
    const float* bv = (const float*)d_in[6];
    const float* Wo = (const float*)d_in[7];
    const float* bo = (const float*)d_in[8];
    float* out = (float*)d_out;

    float *Q, *K, *V, *C;
    cudaGetSymbolAddress((void**)&Q, g_Q);
    cudaGetSymbolAddress((void**)&K, g_Kp);
    cudaGetSymbolAddress((void**)&V, g_Vp);
    cudaGetSymbolAddress((void**)&C, g_ctx);

    qkv_gemm<<<dim3(DMODEL / GBN, ROWS / GBM, 3), 256>>>(
        x, Wq, bq, Q, Wk, bk, K, Wv, bv, V);

    cudaFuncSetAttribute(attn_kernel, cudaFuncAttributeMaxDynamicSharedMemorySize,
                         ATTN_SMEM_BYTES);
    attn_kernel<<<dim3(SEQ / TQ, BH), ATHREADS, ATTN_SMEM_BYTES>>>(Q, K, V, C);

    out_gemm<<<dim3(DMODEL / GBN, ROWS / GBM), 256>>>(C, Wo, bo, out);
}

// round 11
// speedup vs baseline: 1.7129x; 1.7129x over previous
#include <cuda_runtime.h>
#include <cuda_bf16.h>
#include <math.h>

#define BATCH   2
#define SEQ     2048
#define DMODEL  1024
#define NHEAD   16
#define HDIM    64
#define BH      (BATCH*NHEAD)      // 32
#define ROWS    (BATCH*SEQ)        // 4096
#define U_TOP   38                 // int(5 * ln(2048)) = 38
#define CCAP    192                // candidate buffer per row

typedef unsigned long long ull;

// ---- packed f32x2 helpers ---------------------------------------------------
__device__ __forceinline__ ull pk2(float x, float y) {
    ull r; asm("mov.b64 %0, {%1, %2};" : "=l"(r) : "f"(x), "f"(y)); return r;
}
__device__ __forceinline__ void ffma2(ull& d, ull a, ull b) {
    asm("fma.rn.f32x2 %0, %1, %2, %0;" : "+l"(d) : "l"(a), "l"(b));
}
__device__ __forceinline__ float2 up2(ull v) {
    float2 f; asm("mov.b64 {%0, %1}, %2;" : "=f"(f.x), "=f"(f.y) : "l"(v)); return f;
}
union f4u { float4 f; ull u[2]; };

// ---------------- scratch ----------------------------------------------------
__device__ __align__(256) float g_Q[ROWS * DMODEL];
__device__ __align__(256) float g_Kp[ROWS * DMODEL];
__device__ __align__(256) float g_Vp[ROWS * DMODEL];
__device__ __align__(256) float g_ctx[ROWS * DMODEL];

// =================== FFMA2 SGEMM, 16m x 8n, register-staged pipeline =========
#define GBM 256
#define GBN 128
#define GBK 16
#define NKC (DMODEL / GBK)    // 64 k-chunks

__device__ __forceinline__
void gemm_body(const float* __restrict__ A, const float* __restrict__ Bw,
               const float* __restrict__ bias, float* __restrict__ C,
               int m0, int n0, int N)
{
    __shared__ float As[GBK][GBM];
    __shared__ float Bs[GBK][GBN];

    const int tid = threadIdx.x;
    const int tx = tid & 15;
    const int ty = tid >> 4;

    // load-thread mapping (A: 4 f4/thread, B: 2 f4/thread)
    const int arow0 = tid >> 2,  akq = tid & 3;    // +64-row steps x4
    const int brow0 = tid >> 2,  bkq = tid & 3;    // +64-row steps x2

    ull acc2[8][8];
#pragma unroll
    for (int i = 0; i < 8; i++)
#pragma unroll
        for (int j = 0; j < 8; j++) acc2[i][j] = 0ull;

    // prefetch chunk 0 into registers
    float4 pa[4], pb[2];
#pragma unroll
    for (int i = 0; i < 4; i++)
        pa[i] = *(const float4*)(A + (size_t)(m0 + arow0 + i * 64) * DMODEL + akq * 4);
#pragma unroll
    for (int i = 0; i < 2; i++)
        pb[i] = *(const float4*)(Bw + (size_t)(n0 + brow0 + i * 64) * DMODEL + bkq * 4);

    for (int c = 0; c < NKC; c++) {
        __syncthreads();                    // previous chunk's consumers done
#pragma unroll
        for (int i = 0; i < 4; i++) {
            int row = arow0 + i * 64;
            As[akq*4+0][row] = pa[i].x; As[akq*4+1][row] = pa[i].y;
            As[akq*4+2][row] = pa[i].z; As[akq*4+3][row] = pa[i].w;
        }
#pragma unroll
        for (int i = 0; i < 2; i++) {
            int row = brow0 + i * 64;
            Bs[bkq*4+0][row] = pb[i].x; Bs[bkq*4+1][row] = pb[i].y;
            Bs[bkq*4+2][row] = pb[i].z; Bs[bkq*4+3][row] = pb[i].w;
        }
        if (c + 1 < NKC) {                  // prefetch next chunk (hidden by compute)
            const int k0 = (c + 1) * GBK;
#pragma unroll
            for (int i = 0; i < 4; i++)
                pa[i] = *(const float4*)(A + (size_t)(m0 + arow0 + i * 64) * DMODEL + k0 + akq * 4);
#pragma unroll
            for (int i = 0; i < 2; i++)
                pb[i] = *(const float4*)(Bw + (size_t)(n0 + brow0 + i * 64) * DMODEL + k0 + bkq * 4);
        }
        __syncthreads();                    // stores visible

#pragma unroll
        for (int kk = 0; kk < GBK; kk++) {
            f4u a4[4];
#pragma unroll
            for (int q = 0; q < 4; q++)
                a4[q].f = *(float4*)&As[kk][ty * 16 + q * 4];
            float bf[8];
            *(float4*)&bf[0] = *(float4*)&Bs[kk][tx * 8];
            *(float4*)&bf[4] = *(float4*)&Bs[kk][tx * 8 + 4];
            ull bd[8];
#pragma unroll
            for (int j = 0; j < 8; j++) bd[j] = pk2(bf[j], bf[j]);
#pragma unroll
            for (int mp = 0; mp < 8; mp++) {
                ull ap = a4[mp >> 1].u[mp & 1];
#pragma unroll
                for (int j = 0; j < 8; j++) ffma2(acc2[mp][j], ap, bd[j]);
            }
        }
    }

    float bc[8];
#pragma unroll
    for (int j = 0; j < 8; j++) bc[j] = bias[n0 + tx * 8 + j];

#pragma unroll
    for (int mp = 0; mp < 8; mp++) {
        const int rowe = m0 + ty * 16 + mp * 2;
        float2 p[8];
#pragma unroll
        for (int j = 0; j < 8; j++) p[j] = up2(acc2[mp][j]);
        float4 e0 = make_float4(p[0].x + bc[0], p[1].x + bc[1], p[2].x + bc[2], p[3].x + bc[3]);
        float4 e1 = make_float4(p[4].x + bc[4], p[5].x + bc[5], p[6].x + bc[6], p[7].x + bc[7]);
        float4 o0 = make_float4(p[0].y + bc[0], p[1].y + bc[1], p[2].y + bc[2], p[3].y + bc[3]);
        float4 o1 = make_float4(p[4].y + bc[4], p[5].y + bc[5], p[6].y + bc[6], p[7].y + bc[7]);
        float* r0 = C + (size_t)rowe * N + n0 + tx * 8;
        float* r1 = C + (size_t)(rowe + 1) * N + n0 + tx * 8;
        *(float4*)(r0)     = e0;  *(float4*)(r0 + 4) = e1;
        *(float4*)(r1)     = o0;  *(float4*)(r1 + 4) = o1;
    }
}

__global__ __launch_bounds__(256)
void qkv_gemm(const float* __restrict__ x,
              const float* __restrict__ Wq, const float* __restrict__ bq, float* __restrict__ Q,
              const float* __restrict__ Wk, const float* __restrict__ bk, float* __restrict__ K,
              const float* __restrict__ Wv, const float* __restrict__ bv, float* __restrict__ V)
{
    const int sel = blockIdx.z;
    const float* W = (sel == 0) ? Wq : (sel == 1) ? Wk : Wv;
    const float* b = (sel == 0) ? bq : (sel == 1) ? bk : bv;
    float*       C = (sel == 0) ? Q  : (sel == 1) ? K  : V;
    gemm_body(x, W, b, C, blockIdx.y * GBM, blockIdx.x * GBN, DMODEL);
}

__global__ __launch_bounds__(256)
void out_gemm(const float* __restrict__ A, const float* __restrict__ W,
              const float* __restrict__ b, float* __restrict__ C)
{
    gemm_body(A, W, b, C, blockIdx.y * GBM, blockIdx.x * GBN, DMODEL);
}

// ---------------- fused ProbSparse attention ---------------------------------
// 512 threads. Phase 1 = R8's measured 4q x 4k tile, KT=512, 2 d-chunks,
// K prefetched through registers. Phase 2: float4-vectorized scans.
#define TQ 16
#define KT 512
#define ATHREADS 512
#define NCC (SEQ / KT * 2)          // 8 chunk-iterations

__device__ __forceinline__ unsigned fkey(float x) {
    unsigned u = __float_as_uint(x);
    return (u & 0x80000000u) ? ~u : (u | 0x80000000u);
}
__device__ __forceinline__ float unfkey(unsigned k) {
    unsigned u = (k & 0x80000000u) ? (k ^ 0x80000000u) : ~k;
    return __uint_as_float(u);
}

__device__ unsigned radix_select(const float* __restrict__ Srow,
                                 unsigned* __restrict__ myhist, int lane)
{
    unsigned prefix = 0;
    int remaining = U_TOP;
    for (int pass = 0; pass < 4; pass++) {
        const int shift = 24 - pass * 8;
#pragma unroll
        for (int j = 0; j < 8; j++) myhist[lane * 8 + j] = 0;
        __syncwarp();
        for (int i = lane; i < SEQ; i += 32) {
            unsigned key = fkey(Srow[i]);
            bool ok = (pass == 0) || ((key >> (shift + 8)) == prefix);
            if (ok) atomicAdd(&myhist[(key >> shift) & 255], 1u);
        }
        __syncwarp();
        unsigned psum = 0;
#pragma unroll
        for (int j = 0; j < 8; j++) psum += myhist[lane * 8 + j];
        unsigned c = psum;
#pragma unroll
        for (int off = 1; off < 32; off <<= 1) {
            unsigned o = __shfl_down_sync(0xffffffffu, c, off);
            if (lane + off < 32) c += o;
        }
        unsigned mk = __ballot_sync(0xffffffffu, c >= (unsigned)remaining);
        int lsel = 31 - __clz(mk);
        int digit = 0, newrem = remaining;
        if (lane == lsel) {
            unsigned cum = c - psum;
            for (int j = 7; j >= 0; j--) {
                unsigned hv = myhist[lsel * 8 + j];
                cum += hv;
                if (cum >= (unsigned)remaining) {
                    digit = lsel * 8 + j;
                    newrem = remaining - (int)(cum - hv);
                    break;
                }
            }
        }
        digit  = __shfl_sync(0xffffffffu, digit, lsel);
        newrem = __shfl_sync(0xffffffffu, newrem, lsel);
        prefix = (prefix << 8) | (unsigned)digit;
        remaining = newrem;
        __syncwarp();
    }
    return prefix;
}

// smem: S[16*2048] | Qs[16*64] | Ks[512*32 swizzled] | wbuf[16 warps * 384 u32]
#define ATTN_SMEM_BYTES ((TQ*SEQ + TQ*64 + KT*32) * 4 + 16*384*4)

__global__ __launch_bounds__(ATHREADS)
void attn_kernel(const float* __restrict__ Q, const float* __restrict__ K,
                 const float* __restrict__ V, float* __restrict__ ctx)
{
    extern __shared__ char smraw[];
    float*    S    = (float*)smraw;
    float*    Qs   = S  + TQ * SEQ;
    float*    Ks   = Qs + TQ * 64;                 // 512 rows x 32 floats, swizzled
    unsigned* wbuf = (unsigned*)(Ks + KT * 32);    // 16 * 384

    const int tid = threadIdx.x;
    const int qt  = blockIdx.x;
    const int bh  = blockIdx.y;
    const int b   = bh >> 4, h = bh & 15;
    const int q0  = qt * TQ;

    const float* Qbase = Q + ((size_t)b * SEQ + q0) * DMODEL + h * HDIM;
    const float* Kbase = K + ((size_t)b * SEQ) * DMODEL + h * HDIM;
    const float* Vbase = V + ((size_t)b * SEQ) * DMODEL + h * HDIM;

    if (tid < 256) {
        int row = tid >> 4, c4 = tid & 15;
        *(float4*)(Qs + row * 64 + c4 * 4) =
            *(const float4*)(Qbase + (size_t)row * DMODEL + c4 * 4);
    }

    // ---- phase 1: scores, 4q x 4k per thread ----
    const int kq  = tid & 127;
    const int qg  = tid >> 7;
    const int swz = kq & 7;

    const int prow = tid >> 3;
    const int pd4  = tid & 7;

    float4 st[8];
#pragma unroll
    for (int i = 0; i < 8; i++) {
        int row = i * 64 + prow;
        st[i] = *(const float4*)(Kbase + (size_t)row * DMODEL + pd4 * 4);
    }

    ull acc2[4][4];

    for (int cc = 0; cc < NCC; cc++) {
        const int ch = cc & 1;
        const int kb = (cc >> 1) * KT;

        __syncthreads();
#pragma unroll
        for (int i = 0; i < 8; i++) {
            int row = i * 64 + prow;
            *(float4*)(Ks + row * 32 + ((pd4 ^ ((row >> 2) & 7)) << 2)) = st[i];
        }
        if (cc + 1 < NCC) {
            const int nch = (cc + 1) & 1;
            const int nkb = ((cc + 1) >> 1) * KT;
#pragma unroll
            for (int i = 0; i < 8; i++) {
                int row = i * 64 + prow;
                st[i] = *(const float4*)(Kbase + (size_t)(nkb + row) * DMODEL
                                         + nch * 32 + pd4 * 4);
            }
        }
        __syncthreads();

        if (ch == 0) {
#pragma unroll
            for (int j = 0; j < 4; j++)
#pragma unroll
                for (int i = 0; i < 4; i++) acc2[j][i] = 0ull;
        }

#pragma unroll
        for (int d4 = 0; d4 < 8; d4++) {
            f4u kv[4];
#pragma unroll
            for (int i = 0; i < 4; i++)
                kv[i].f = *(float4*)(Ks + (kq * 4 + i) * 32 + ((d4 ^ swz) << 2));
#pragma unroll
            for (int j = 0; j < 4; j++) {
                f4u qv;
                qv.f = *(float4*)(Qs + (qg * 4 + j) * 64 + ch * 32 + (d4 << 2));
#pragma unroll
                for (int i = 0; i < 4; i++) {
                    ffma2(acc2[j][i], qv.u[0], kv[i].u[0]);
                    ffma2(acc2[j][i], qv.u[1], kv[i].u[1]);
                }
            }
        }

        if (ch == 1) {
#pragma unroll
            for (int j = 0; j < 4; j++) {
                float2 r0 = up2(acc2[j][0]), r1 = up2(acc2[j][1]);
                float2 r2 = up2(acc2[j][2]), r3 = up2(acc2[j][3]);
                float4 o = make_float4((r0.x + r0.y) * 0.125f, (r1.x + r1.y) * 0.125f,
                                       (r2.x + r2.y) * 0.125f, (r3.x + r3.y) * 0.125f);
                *(float4*)(S + (size_t)(qg * 4 + j) * SEQ + kb + kq * 4) = o;
            }
        }
    }
    __syncthreads();

    // ---- phase 2: 1 row per warp, float4-vectorized scans ----
    const int lane = tid & 31, wid = tid >> 5;
    const unsigned lmlt = (1u << lane) - 1u;
    unsigned* chk = wbuf + wid * 384;
    int*      chi = (int*)(chk + CCAP);
    unsigned* myhist = chk;

    {
        const int q = wid;
        const float* Srow = S + (size_t)q * SEQ;

        // pass 1: row max + per-lane-max threshold (float4)
        float lm = -1e30f;
        for (int i = lane; i < SEQ / 4; i += 32) {
            float4 v = ((const float4*)Srow)[i];
            lm = fmaxf(lm, fmaxf(fmaxf(v.x, v.y), fmaxf(v.z, v.w)));
        }
        float m = lm, tmin = lm;
#pragma unroll
        for (int off = 16; off; off >>= 1) {
            m    = fmaxf(m,    __shfl_xor_sync(0xffffffffu, m,    off));
            tmin = fminf(tmin, __shfl_xor_sync(0xffffffffu, tmin, off));
        }
        const unsigned Tk = fkey(tmin);

        // pass 2: candidate compaction (float4 loads, 4 ordered ballots / 128)
        int cnt = 0;
        for (int base = 0; base < SEQ; base += 128) {
            float4 v = *(const float4*)(Srow + base + lane * 4);
            unsigned k4[4] = { fkey(v.x), fkey(v.y), fkey(v.z), fkey(v.w) };
#pragma unroll
            for (int c = 0; c < 4; c++) {
                bool kp = k4[c] >= Tk;
                unsigned bm = __ballot_sync(0xffffffffu, kp);
                if (kp) {
                    int pos = cnt + __popc(bm & lmlt);
                    if (pos < CCAP) { chk[pos] = k4[c]; chi[pos] = base + lane * 4 + c; }
                }
                cnt += __popc(bm);
            }
        }
        __syncwarp();

        const bool okc = (cnt >= U_TOP && cnt <= CCAP);
        unsigned kth;
        if (okc) {
            unsigned ck[6];
#pragma unroll
            for (int t = 0; t < 6; t++) {
                int p = lane + t * 32;
                ck[t] = (p < cnt) ? chk[p] : 0u;
            }
            unsigned lo = Tk, hi = fkey(m);
            while (lo < hi) {
                unsigned mid = lo + ((hi - lo + 1) >> 1);
                int c = 0;
#pragma unroll
                for (int t = 0; t < 6; t++) c += (ck[t] >= mid) ? 1 : 0;
                c = __reduce_add_sync(0xffffffffu, c);
                if (c >= U_TOP) lo = mid; else hi = mid - 1;
            }
            kth = lo;
        } else {
            kth = radix_select(Srow, myhist, lane);
        }

        // pass 3: final (idx, weight) list + exp-sum
        float lsum = 0.f;
        int nk = 0;
        if (okc) {
            for (int base = 0; base < cnt; base += 32) {
                int p = base + lane;
                unsigned key = (p < cnt) ? chk[p] : 0u;
                int idx      = (p < cnt) ? chi[p] : 0;
                __syncwarp();
                bool kp = (p < cnt) && (key >= kth);
                unsigned bm = __ballot_sync(0xffffffffu, kp);
                if (kp) {
                    float w = __expf(unfkey(key) - m);
                    lsum += w;
                    int pos = nk + __popc(bm & lmlt);
                    chi[pos] = idx;
                    chk[pos] = __float_as_uint(w);
                }
                nk += __popc(bm);
            }
        } else {
            for (int base = 0; base < SEQ; base += 32) {
                int i = base + lane;
                float s = Srow[i];
                bool kp = fkey(s) >= kth;
                unsigned bm = __ballot_sync(0xffffffffu, kp);
                if (kp) {
                    float w = __expf(s - m);
                    lsum += w;
                    int pos = nk + __popc(bm & lmlt);
                    if (pos < CCAP) { chi[pos] = i; chk[pos] = __float_as_uint(w); }
                }
                nk += __popc(bm);
            }
        }
        __syncwarp();
#pragma unroll
        for (int off = 16; off; off >>= 1)
            lsum += __shfl_xor_sync(0xffffffffu, lsum, off);
        const float scale = 1.f / lsum;

        // pass 4: sparse AV gather
        float c0 = 0.f, c1 = 0.f;
        if (nk <= CCAP) {
#pragma unroll 4
            for (int j = 0; j < nk; j++) {
                int kkidx = chi[j];
                float w = __uint_as_float(chk[j]);
                const float* vr = Vbase + (size_t)kkidx * DMODEL;
                c0 += w * vr[lane];
                c1 += w * vr[lane + 32];
            }
        } else {
            for (int i = 0; i < SEQ; i++) {
                float s = Srow[i];
                if (fkey(s) >= kth) {
                    float w = __expf(s - m);
                    const float* vr = Vbase + (size_t)i * DMODEL;
                    c0 += w * vr[lane];
                    c1 += w * vr[lane + 32];
                }
            }
        }
        float* orow = ctx + ((size_t)b * SEQ + q0 + q) * DMODEL + h * HDIM;
        orow[lane]      = c0 * scale;
        orow[lane + 32] = c1 * scale;
    }
}

// ---------------- launch ----------------------------------------------------
extern "C" void kernel_launch(void* const* d_in, const int* in_sizes, int n_in,
                              void* d_out, int out_size)
{
    const float* x  = (const float*)d_in[0];
    const float* Wq = (const float*)d_in[1];
    const float* bq = (const float*)d_in[2];
    const float* Wk = (const float*)d_in[3];
    const float* bk = (const float*)d_in[4];
    const float* Wv = (const float*)d_in[5];
    const float* bv = (const float*)d_in[6];
    const float* Wo = (const float*)d_in[7];
    const float* bo = (const float*)d_in[8];
    float* out = (float*)d_out;

    float *Q, *K, *V, *C;
    cudaGetSymbolAddress((void**)&Q, g_Q);
    cudaGetSymbolAddress((void**)&K, g_Kp);
    cudaGetSymbolAddress((void**)&V, g_Vp);
    cudaGetSymbolAddress((void**)&C, g_ctx);

    qkv_gemm<<<dim3(DMODEL / GBN, ROWS / GBM, 3), 256>>>(
        x, Wq, bq, Q, Wk, bk, K, Wv, bv, V);

    cudaFuncSetAttribute(attn_kernel, cudaFuncAttributeMaxDynamicSharedMemorySize,
                         ATTN_SMEM_BYTES);
    attn_kernel<<<dim3(SEQ / TQ, BH), ATHREADS, ATTN_SMEM_BYTES>>>(Q, K, V, C);

    out_gemm<<<dim3(DMODEL / GBN, ROWS / GBM), 256>>>(C, Wo, bo, out);
}